// round 3
// baseline (speedup 1.0000x reference)
#include <cuda_runtime.h>

// FasterTensorProduct: out[b, n1, n2, :] is bilinear in (in_[b,n2,:], sh[b,n1,0..3]).
// Factor: P[b,n2,s,:] = y(x_{b,n2}, e_s); then out = sum_s sh[b,n1,s] * P[b,n2,s,:].
//
// Dims: M0E=64, M1O=32, M1E=32, M0O=16, IN_DIM=OUT_DIM=272, B=4, N=128.
// Weights (flat, row-major, each block scaled by 1/sqrt(rows)):
//   W0e at 0     : (96,64)
//   W1o at 6144  : (128,32)
//   W1e at 10240 : (80,32)
//   W0o at 12800 : (48,16)

#define B_DIM 4
#define N_DIM 128
#define IO_DIM 272

__global__ __launch_bounds__(272) void ftp_kernel(
    const float* __restrict__ in_, const float* __restrict__ sh,
    const float* __restrict__ w, float* __restrict__ out)
{
    __shared__ float  xs[IO_DIM];     // input row for this (b, n2)
    __shared__ float4 shs[N_DIM];     // sh rows for this b
    __shared__ float4 P4[IO_DIM];     // P4[o] = (P[s=0][o], P[1][o], P[2][o], P[3][o])

    const int tid = threadIdx.x;
    const int n2  = blockIdx.x;
    const int b   = blockIdx.y;

    // ---- phase 0: cooperative loads ----
    const float* xrow = in_ + (size_t)(b * N_DIM + n2) * IO_DIM;
    xs[tid] = xrow[tid];
    for (int i = tid; i < N_DIM; i += 272)
        shs[i] = reinterpret_cast<const float4*>(sh)[b * N_DIM + i];
    __syncthreads();

    // ---- phase 1: compute P4[o] for o = tid ----
    const float inv2 = 0.7071067811865476f;   // 1/sqrt(2)
    const float inv3 = 0.5773502691896258f;   // 1/sqrt(3)

    float p0, p1, p2, p3;
    const int o = tid;

    if (o < 64) {
        // y0e region. out0e = [x0e*sh0, (x1o . sh1)/sqrt3], W0e (96,64), scale 1/sqrt(96)
        const float s = 0.10206207261596575f;
        float a0 = 0.f;
        #pragma unroll
        for (int k = 0; k < 64; k++) a0 += xs[k] * w[k * 64 + o];
        float a1 = 0.f, a2 = 0.f, a3 = 0.f;
        #pragma unroll
        for (int m = 0; m < 32; m++) {
            float wv = w[(64 + m) * 64 + o];
            a1 += xs[64 + 3 * m + 0] * wv;
            a2 += xs[64 + 3 * m + 1] * wv;
            a3 += xs[64 + 3 * m + 2] * wv;
        }
        p0 = a0 * s;
        p1 = a1 * (s * inv3);
        p2 = a2 * (s * inv3);
        p3 = a3 * (s * inv3);
    } else if (o < 160) {
        // y1o region: o = 64 + oo*3 + cp. W1o (128,32) at 6144, scale 1/sqrt(128)
        // out1o rows: [0:64) x0e*sh1[c], [64:96) x1o*sh0, [96:128) cross(x1e, sh1)/sqrt2
        const float s  = 0.08838834764831845f;
        const int  t  = o - 64;
        const int  oo = t / 3;
        const int  cp = t - 3 * oo;
        const int  ca = (cp + 1) % 3;
        const int  cb = (cp + 2) % 3;
        const float* w1 = w + 6144;
        float A = 0.f, Bacc = 0.f, Ca = 0.f, Cb = 0.f;
        #pragma unroll
        for (int k = 0; k < 64; k++) Bacc += xs[k] * w1[k * 32 + oo];
        #pragma unroll
        for (int m = 0; m < 32; m++) {
            A += xs[64 + 3 * m + cp] * w1[(64 + m) * 32 + oo];
            float wv = w1[(96 + m) * 32 + oo];
            // cross(x1e, e_c)[cp]:  c=ca -> -x1e[cb],  c=cb -> +x1e[ca]
            Ca += xs[160 + 3 * m + cb] * wv;
            Cb += xs[160 + 3 * m + ca] * wv;
        }
        p0 = A * s;                          // s = 0 (sh0 = 1): only x1o*sh0 rows
        float vB = Bacc * s;                 // s = cp+1: x0e rows land in column cp
        float vA = -Ca * (s * inv2);         // s = ca+1
        float vC =  Cb * (s * inv2);         // s = cb+1
        p1 = (cp == 0) ? vB : ((ca == 0) ? vA : vC);
        p2 = (cp == 1) ? vB : ((ca == 1) ? vA : vC);
        p3 = (cp == 2) ? vB : ((ca == 2) ? vA : vC);
    } else if (o < 256) {
        // y1e region: o = 160 + oo*3 + cp. W1e (80,32) at 10240, scale 1/sqrt(80)
        // out1e rows: [0:32) cross(x1o, sh1)/sqrt2, [32:64) x1e*sh0, [64:80) x0o*sh1[c]
        const float s  = 0.11180339887498949f;
        const int  t  = o - 160;
        const int  oo = t / 3;
        const int  cp = t - 3 * oo;
        const int  ca = (cp + 1) % 3;
        const int  cb = (cp + 2) % 3;
        const float* w2 = w + 10240;
        float A = 0.f, Bacc = 0.f, Ca = 0.f, Cb = 0.f;
        #pragma unroll
        for (int m = 0; m < 32; m++) {
            A += xs[160 + 3 * m + cp] * w2[(32 + m) * 32 + oo];
            float wv = w2[m * 32 + oo];
            Ca += xs[64 + 3 * m + cb] * wv;   // cross(x1o, e_ca)[cp] = -x1o[cb]
            Cb += xs[64 + 3 * m + ca] * wv;   // cross(x1o, e_cb)[cp] = +x1o[ca]
        }
        #pragma unroll
        for (int k = 0; k < 16; k++) Bacc += xs[256 + k] * w2[(64 + k) * 32 + oo];
        p0 = A * s;
        float vB = Bacc * s;
        float vA = -Ca * (s * inv2);
        float vC =  Cb * (s * inv2);
        p1 = (cp == 0) ? vB : ((ca == 0) ? vA : vC);
        p2 = (cp == 1) ? vB : ((ca == 1) ? vA : vC);
        p3 = (cp == 2) ? vB : ((ca == 2) ? vA : vC);
    } else {
        // y0o region: o = 256 + oy. W0o (48,16) at 12800, scale 1/sqrt(48)
        // out0o = [(x1e . sh1)/sqrt3, x0o*sh0]
        const float s  = 0.14433756729740645f;
        const int  oy = o - 256;
        const float* w3 = w + 12800;
        float a0 = 0.f;
        #pragma unroll
        for (int k = 0; k < 16; k++) a0 += xs[256 + k] * w3[(32 + k) * 16 + oy];
        float a1 = 0.f, a2 = 0.f, a3 = 0.f;
        #pragma unroll
        for (int m = 0; m < 32; m++) {
            float wv = w3[m * 16 + oy];
            a1 += xs[160 + 3 * m + 0] * wv;
            a2 += xs[160 + 3 * m + 1] * wv;
            a3 += xs[160 + 3 * m + 2] * wv;
        }
        p0 = a0 * s;
        p1 = a1 * (s * inv3);
        p2 = a2 * (s * inv3);
        p3 = a3 * (s * inv3);
    }

    P4[o] = make_float4(p0, p1, p2, p3);
    __syncthreads();

    // ---- phase 2: fan-out over n1 (write-bandwidth bound) ----
    const int o4 = tid % 68;   // which float4 of the 272-wide output row
    const int g  = tid / 68;   // 0..3
    float4 q0 = P4[o4 * 4 + 0];
    float4 q1 = P4[o4 * 4 + 1];
    float4 q2 = P4[o4 * 4 + 2];
    float4 q3 = P4[o4 * 4 + 3];
    float4* __restrict__ outv = reinterpret_cast<float4*>(out);

    #pragma unroll 8
    for (int n1 = g; n1 < N_DIM; n1 += 4) {
        float4 s4 = shs[n1];
        float4 r;
        r.x = q0.x * s4.x + q0.y * s4.y + q0.z * s4.z + q0.w * s4.w;
        r.y = q1.x * s4.x + q1.y * s4.y + q1.z * s4.z + q1.w * s4.w;
        r.z = q2.x * s4.x + q2.y * s4.y + q2.z * s4.z + q2.w * s4.w;
        r.w = q3.x * s4.x + q3.y * s4.y + q3.z * s4.z + q3.w * s4.w;
        outv[((size_t)(b * N_DIM + n1) * N_DIM + n2) * 68 + o4] = r;
    }
}

extern "C" void kernel_launch(void* const* d_in, const int* in_sizes, int n_in,
                              void* d_out, int out_size) {
    // Defensive input mapping by element count (in_: 139264, sh: 2048, weight: 13568)
    const float* in_ = nullptr;
    const float* sh  = nullptr;
    const float* w   = nullptr;
    for (int i = 0; i < n_in; i++) {
        if (in_sizes[i] == B_DIM * N_DIM * IO_DIM)      in_ = (const float*)d_in[i];
        else if (in_sizes[i] == B_DIM * N_DIM * 4)      sh  = (const float*)d_in[i];
        else if (in_sizes[i] == 13568)                  w   = (const float*)d_in[i];
    }
    if (!in_) in_ = (const float*)d_in[0];
    if (!sh)  sh  = (const float*)d_in[1];
    if (!w)   w   = (const float*)d_in[2];

    float* out = (float*)d_out;
    dim3 grid(N_DIM, B_DIM);
    ftp_kernel<<<grid, 272>>>(in_, sh, w, out);
}